// round 13
// baseline (speedup 1.0000x reference)
#include <cuda_runtime.h>
#include <math.h>

#define N_NODES 20000
#define N_EDGES 320000

// ---------------- scratch (device globals) ----------------
// g_sv per node: s[0:64], v planar: 64 + 64*i + u
__device__ float g_sv[N_NODES * 256];
// g_agg per node: A[0:64], D[64:128], B planes 128+64*i+u, C planes 320+64*i+u
__device__ float g_agg[N_NODES * 512];
__device__ float g_gate[N_NODES * 64];
// CSR by dst
__device__ int g_cnt[N_NODES];
__device__ int g_off[N_NODES];
__device__ int g_cur[N_NODES];
__device__ int g_eid[N_EDGES];

__device__ __forceinline__ float silu_n(float x) {
    return 1.679177f * x * (1.0f / (1.0f + __expf(-x)));
}

// ---------------- f32x2 packed-FMA helpers (Blackwell FFMA2) ----------------
typedef unsigned long long u64t;
__device__ __forceinline__ u64t pkdup(float v) {
    u64t r; asm("mov.b64 %0, {%1, %1};" : "=l"(r) : "f"(v)); return r;
}
__device__ __forceinline__ void fma2(u64t& d, u64t a, u64t b) {
    asm("fma.rn.f32x2 %0, %1, %2, %0;" : "+l"(d) : "l"(a), "l"(b));
}
__device__ __forceinline__ float2 up2(u64t v) {
    float2 r; asm("mov.b64 {%0, %1}, %2;" : "=f"(r.x), "=f"(r.y) : "l"(v)); return r;
}

// ---------------- K1: lin1, persistent blocks, weights staged in smem ----------------
__global__ void __launch_bounds__(256)
k1_lin1(const float* __restrict__ ns, const float* __restrict__ nv,
        const float* __restrict__ W1s, const float* __restrict__ W1v) {
    __shared__ float sWs[4096];
    __shared__ float sWv[4096];
    __shared__ float sIn[4][256];
    int tid = threadIdx.x;
    for (int i = tid; i < 4096; i += 256) {
        sWs[i] = W1s[i] * 0.125f;
        sWv[i] = W1v[i] * 0.125f;
    }
    __syncthreads();
    int w = tid & 63, q = tid >> 6;
    const int ntile = N_NODES / 4;

    for (int tile = blockIdx.x; tile < ntile; tile += gridDim.x) {
        int n0 = tile * 4;
        __syncthreads();
        for (int idx = tid; idx < 1024; idx += 256) {
            int q2 = idx >> 8, r = idx & 255;
            sIn[q2][r] = (r < 64) ? ns[(size_t)(n0 + q2) * 64 + r]
                                  : nv[(size_t)(n0 + q2) * 192 + (r - 64)];
        }
        __syncthreads();
        const float* si = sIn[q];
        float as = 0.f, a0 = 0.f, a1 = 0.f, a2 = 0.f;
#pragma unroll 4
        for (int u = 0; u < 64; u++) {
            float ws = sWs[u * 64 + w];
            float wv = sWv[u * 64 + w];
            as += si[u] * ws;
            a0 += si[64 + 3 * u + 0] * wv;
            a1 += si[64 + 3 * u + 1] * wv;
            a2 += si[64 + 3 * u + 2] * wv;
        }
        float* o = g_sv + (size_t)(n0 + q) * 256;
        o[w] = as;
        o[64 + w] = a0;
        o[128 + w] = a1;
        o[192 + w] = a2;
    }
}

// ---------------- CSR build ----------------
__global__ void kc_zero() {
    int i = blockIdx.x * blockDim.x + threadIdx.x;
    if (i < N_NODES) g_cnt[i] = 0;
}
__global__ void kc_count(const int* __restrict__ edst) {
    int e = blockIdx.x * blockDim.x + threadIdx.x;
    if (e < N_EDGES) {
        int d = min(max(edst[e], 0), N_NODES - 1);
        atomicAdd(&g_cnt[d], 1);
    }
}
__global__ void __launch_bounds__(1024) kc_scan() {
    __shared__ int part[1024];
    int tid = threadIdx.x;
    const int PER = 20;  // 1024*20 = 20480 >= 20000
    int base = tid * PER;
    int s = 0;
    for (int i = 0; i < PER; i++) {
        int idx = base + i;
        if (idx < N_NODES) s += g_cnt[idx];
    }
    part[tid] = s;
    __syncthreads();
    for (int d = 1; d < 1024; d <<= 1) {
        int v = 0;
        if (tid >= d) v = part[tid - d];
        __syncthreads();
        if (tid >= d) part[tid] += v;
        __syncthreads();
    }
    int run = part[tid] - s;  // exclusive prefix for this thread's range
    for (int i = 0; i < PER; i++) {
        int idx = base + i;
        if (idx < N_NODES) {
            g_off[idx] = run;
            g_cur[idx] = run;
            run += g_cnt[idx];
        }
    }
}
__global__ void kc_scatter(const int* __restrict__ edst) {
    int e = blockIdx.x * blockDim.x + threadIdx.x;
    if (e < N_EDGES) {
        int d = min(max(edst[e], 0), N_NODES - 1);
        int pos = atomicAdd(&g_cur[d], 1);
        g_eid[pos] = e;
    }
}

// ---------------- K3: fused dst-grouped edge MLP + register aggregation ----------------
// Warp n owns dst node n. Processes its CSR edge list in chunks of 8 through the
// proven MLP core; accumulates A/D/B/C in registers; single plain store per node.
// smem floats: sW0 512 + sW1 4096 + sW2 16384 + 16 warps * 752 = 33024 -> 132096 B
#define K3_SMEM 132096
__global__ void __launch_bounds__(512, 1)
k3_fused(const float* __restrict__ esh, const float* __restrict__ emb,
         const int* __restrict__ esrc,
         const float* __restrict__ W0, const float* __restrict__ W1,
         const float* __restrict__ W2) {
    extern __shared__ float sm[];
    float* sW0 = sm;           // [8][64]   pre-scaled 1/sqrt(8)
    float* sW1 = sm + 512;     // [64][64]  pre-scaled 0.125
    float* sW2 = sm + 4608;    // [64][256] pre-scaled 0.125
    int tid = threadIdx.x;
    for (int i = tid; i < 512; i += 512)   sW0[i] = W0[i] * 0.35355339059327373f;
    for (int i = tid; i < 4096; i += 512)  sW1[i] = W1[i] * 0.125f;
    for (int i = tid; i < 16384; i += 512) sW2[i] = W2[i] * 0.125f;
    __syncthreads();

    int warp = tid >> 5, lane = tid & 31;
    float* pH  = sm + 20992 + warp * 752;  // [row 64][stride 10]
    float* pEB = pH + 640;                 // 64: emb for 8 edges
    float* pSH = pEB + 64;                 // 32: sh float4 for 8 edges
    int*   pIX = (int*)(pSH + 32);         // 16: eid[8], src[8]

    const float inv_sqrt3 = 0.57735026918962576f;
    int n = blockIdx.x * 16 + warp;        // grid 1250 * 16 warps = 20000 exactly
    int beg = g_off[n];
    int end = beg + g_cnt[n];

    float aA[2] = {0.f, 0.f}, aD[2] = {0.f, 0.f};
    float aB0[2] = {0.f, 0.f}, aB1[2] = {0.f, 0.f}, aB2[2] = {0.f, 0.f};
    float aC0[2] = {0.f, 0.f}, aC1[2] = {0.f, 0.f}, aC2[2] = {0.f, 0.f};

    for (int p = beg; p < end; p += 8) {
        int nch = min(8, end - p);
        // ---- edge meta: 8 (padded) edges of this dst ----
        if (lane < 8) {
            int e = __ldg(g_eid + p + ((lane < nch) ? lane : 0));  // pad with first edge
            pIX[lane] = e;
            pIX[8 + lane] = min(max(__ldg(esrc + e), 0), N_NODES - 1);
            ((float4*)pSH)[lane] = __ldg((const float4*)esh + e);
        }
        __syncwarp();
        {
            int e_lo = pIX[lane >> 3];
            int e_hi = pIX[4 + (lane >> 3)];
            pEB[lane]      = __ldg(emb + (size_t)e_lo * 8 + (lane & 7));
            pEB[32 + lane] = __ldg(emb + (size_t)e_hi * 8 + (lane & 7));
        }
        __syncwarp();

        // ---- fc0: h0[j][e] (stride 10); lane computes j = lane, lane+32 ----
#pragma unroll
        for (int e = 0; e < 8; e++) {
            float eb[8];
#pragma unroll
            for (int b = 0; b < 8; b++) eb[b] = pEB[e * 8 + b];
#pragma unroll
            for (int jj = 0; jj < 2; jj++) {
                int j = lane + 32 * jj;
                float a = 0.f;
#pragma unroll
                for (int b = 0; b < 8; b++) a += eb[b] * sW0[b * 64 + j];
                pH[j * 10 + e] = silu_n(a);
            }
        }
        __syncwarp();

        // ---- fc1: edge-paired FFMA2 ----
        u64t h1[2][4] = {{0ull,0ull,0ull,0ull},{0ull,0ull,0ull,0ull}};
#pragma unroll 4
        for (int k = 0; k < 64; k++) {
            u64t wd0 = pkdup(sW1[k * 64 + lane]);
            u64t wd1 = pkdup(sW1[k * 64 + lane + 32]);
#pragma unroll
            for (int ep = 0; ep < 4; ep++) {
                u64t hp = *(const u64t*)(pH + k * 10 + 2 * ep);
                fma2(h1[0][ep], wd0, hp);
                fma2(h1[1][ep], wd1, hp);
            }
        }
        __syncwarp();
#pragma unroll
        for (int kk = 0; kk < 2; kk++)
#pragma unroll
            for (int ep = 0; ep < 4; ep++) {
                float2 v = up2(h1[kk][ep]);
                pH[(lane + 32 * kk) * 10 + 2 * ep]     = silu_n(v.x);
                pH[(lane + 32 * kk) * 10 + 2 * ep + 1] = silu_n(v.y);
            }
        __syncwarp();

        // ---- fc2: lane owns c = lane + 32j; acc[j][edge-pair] ----
        u64t acc[8][4];
#pragma unroll
        for (int c = 0; c < 8; c++)
#pragma unroll
            for (int ep = 0; ep < 4; ep++) acc[c][ep] = 0ull;
#pragma unroll 2
        for (int k = 0; k < 64; k++) {
            u64t wd[8];
#pragma unroll
            for (int c = 0; c < 8; c++)
                wd[c] = pkdup(sW2[k * 256 + lane + 32 * c]);
#pragma unroll
            for (int ep = 0; ep < 4; ep++) {
                u64t hp = *(const u64t*)(pH + k * 10 + 2 * ep);
#pragma unroll
                for (int c = 0; c < 8; c++) fma2(acc[c][ep], wd[c], hp);
            }
        }
        __syncwarp();

        // ---- accumulate valid edges into running registers ----
#pragma unroll
        for (int e = 0; e < 8; e++) {
            if (e >= nch) break;
            int src = pIX[8 + e];
            float y0 = pSH[4 * e + 0], Y1 = pSH[4 * e + 1];
            float Y2 = pSH[4 * e + 2], Y3 = pSH[4 * e + 3];
            const float* sv = g_sv + (size_t)src * 256;
#pragma unroll
            for (int half = 0; half < 2; half++) {
                int u = lane + 32 * half;
                float2 tA = up2(acc[half][e >> 1]);
                float2 tB = up2(acc[half + 2][e >> 1]);
                float2 tC = up2(acc[half + 4][e >> 1]);
                float2 tD = up2(acc[half + 6][e >> 1]);
                float wA = (e & 1) ? tA.y : tA.x;
                float wB = (e & 1) ? tB.y : tB.x;
                float wC = (e & 1) ? tC.y : tC.x;
                float wD = (e & 1) ? tD.y : tD.x;
                float sA = __ldg(sv + u);
                float v0 = __ldg(sv + 64 + u);
                float v1 = __ldg(sv + 128 + u);
                float v2 = __ldg(sv + 192 + u);
                aA[half] += wA * sA * y0;
                aD[half] += wD * (v0 * Y1 + v1 * Y2 + v2 * Y3) * inv_sqrt3;
                float bs = wB * sA;
                aB0[half] += bs * Y1;
                aB1[half] += bs * Y2;
                aB2[half] += bs * Y3;
                float cy = wC * y0;
                aC0[half] += cy * v0;
                aC1[half] += cy * v1;
                aC2[half] += cy * v2;
            }
        }
        __syncwarp();
    }

    // ---- single plain store per node (no atomics, no pre-zero needed) ----
    float* ag = g_agg + (size_t)n * 512;
#pragma unroll
    for (int half = 0; half < 2; half++) {
        int u = lane + 32 * half;
        ag[u]       = aA[half];
        ag[64 + u]  = aD[half];
        ag[128 + u] = aB0[half];
        ag[192 + u] = aB1[half];
        ag[256 + u] = aB2[half];
        ag[320 + u] = aC0[half];
        ag[384 + u] = aC1[half];
        ag[448 + u] = aC2[half];
    }
}

// ---------------- K4a: s_h = [agg_s | ns(x)attr] @ Wcat, gates + out_s ----------------
#define K4A_SMEM 221184
__global__ void __launch_bounds__(512)
k4a(const float* __restrict__ ns, const float* __restrict__ attr,
    const float* __restrict__ Wl2s, const float* __restrict__ Wscs,
    float* __restrict__ out) {
    extern __shared__ float sm[];
    float* sW = sm;            // [384][128], pre-scaled
    float* sOp = sW + 49152;   // [384][16]
    int tid = threadIdx.x;
    const float lin2n = 0.08838834764831845f;
    const float scn = 0.0625f;
    for (int i = tid; i < 16384; i += 512) sW[i] = Wl2s[i] * lin2n;
    for (int i = tid; i < 32768; i += 512) sW[16384 + i] = Wscs[i] * scn;
    __syncthreads();

    int w = tid & 127, nh = tid >> 7;
    const int ntile = N_NODES / 16;

    for (int tile = blockIdx.x; tile < ntile; tile += gridDim.x) {
        int n0 = tile * 16;
        {
            int k = tid & 127, q = tid >> 7;
#pragma unroll
            for (int nn = 0; nn < 4; nn++) {
                int node = q * 4 + nn;
                sOp[k * 16 + node] = g_agg[(size_t)(n0 + node) * 512 + k] * 0.0625f;
            }
            for (int idx = tid; idx < 4096; idx += 512) {
                int m = idx >> 4, node = idx & 15;
                sOp[(128 + m) * 16 + node] =
                    ns[(size_t)(n0 + node) * 64 + (m >> 2)] * attr[(size_t)(n0 + node) * 4 + (m & 3)];
            }
        }
        __syncthreads();

        u64t a01 = 0ull, a23 = 0ull;
#pragma unroll 4
        for (int k = 0; k < 384; k++) {
            u64t wd = pkdup(sW[k * 128 + w]);
            ulonglong2 op = *(const ulonglong2*)(sOp + k * 16 + nh * 4);
            fma2(a01, wd, op.x);
            fma2(a23, wd, op.y);
        }
        float2 r01 = up2(a01), r23 = up2(a23);
        float r[4] = {r01.x, r01.y, r23.x, r23.y};
#pragma unroll
        for (int j = 0; j < 4; j++) {
            int n = n0 + nh * 4 + j;
            float val = silu_n(r[j]);
            if (w < 64) out[(size_t)n * 256 + w] = val;
            else        g_gate[(size_t)n * 64 + (w - 64)] = val;
        }
        __syncthreads();
    }
}

// ---------------- K4b: v_h = [agg_v | nv(x)attr] @ Wvcat, gate + out_v ----------------
#define K4B_SMEM 147456
__global__ void __launch_bounds__(512)
k4b(const float* __restrict__ nv, const float* __restrict__ attr,
    const float* __restrict__ Wl2v, const float* __restrict__ Wscv,
    float* __restrict__ out) {
    extern __shared__ float sm[];
    float* sW = sm;            // [384][64], pre-scaled
    float* sOp = sW + 24576;   // [384][8 nodes][4]
    int tid = threadIdx.x;
    const float lin2n = 0.08838834764831845f;
    const float scn = 0.0625f;
    for (int i = tid; i < 8192; i += 512)  sW[i] = Wl2v[i] * lin2n;
    for (int i = tid; i < 16384; i += 512) sW[8192 + i] = Wscv[i] * scn;
    __syncthreads();

    int w = tid & 63, node = tid >> 6;
    const int ntile = N_NODES / 8;

    for (int tile = blockIdx.x; tile < ntile; tile += gridDim.x) {
        int n0 = tile * 8;
        for (int idx = tid; idx < 3072; idx += 512) {
            int k = idx >> 3, nd = idx & 7;
            int n = n0 + nd;
            float o0, o1, o2;
            if (k < 128) {
                const float* p = g_agg + (size_t)n * 512 + ((k < 64) ? (128 + k) : (320 + k - 64));
                o0 = p[0] * 0.0625f; o1 = p[64] * 0.0625f; o2 = p[128] * 0.0625f;
            } else {
                int m = k - 128;
                int u = m >> 2, v = m & 3;
                float av = attr[(size_t)n * 4 + v];
                const float* p = nv + (size_t)n * 192 + u * 3;
                o0 = p[0] * av; o1 = p[1] * av; o2 = p[2] * av;
            }
            *(float4*)(sOp + idx * 4) = make_float4(o0, o1, o2, 0.f);
        }
        __syncthreads();

        u64t a01 = 0ull;
        float a2 = 0.f;
#pragma unroll 4
        for (int k = 0; k < 384; k++) {
            float wk = sW[k * 64 + w];
            u64t wd = pkdup(wk);
            ulonglong2 op = *(const ulonglong2*)(sOp + (k * 8 + node) * 4);
            fma2(a01, wd, op.x);
            float2 t = up2(op.y);
            a2 += wk * t.x;
        }
        int n = n0 + node;
        float gate = g_gate[(size_t)n * 64 + w];
        float2 r = up2(a01);
        float* o = out + (size_t)n * 256 + 64 + 3 * w;
        o[0] = gate * r.x; o[1] = gate * r.y; o[2] = gate * a2;
        __syncthreads();
    }
}

// ---------------- launch ----------------
extern "C" void kernel_launch(void* const* d_in, const int* in_sizes, int n_in,
                              void* d_out, int out_size) {
    const float* node_scalars  = (const float*)d_in[0];
    const float* node_vectors  = (const float*)d_in[1];
    const float* node_attr     = (const float*)d_in[2];
    const float* edge_sh       = (const float*)d_in[3];
    const float* edge_embedded = (const float*)d_in[4];
    const int*   edge_src      = (const int*)d_in[5];
    const int*   edge_dst      = (const int*)d_in[6];
    const float* W_lin1_s      = (const float*)d_in[7];
    const float* W_lin1_v      = (const float*)d_in[8];
    const float* W_fc0         = (const float*)d_in[9];
    const float* W_fc1         = (const float*)d_in[10];
    const float* W_fc2         = (const float*)d_in[11];
    const float* W_lin2_s      = (const float*)d_in[12];
    const float* W_lin2_v      = (const float*)d_in[13];
    const float* W_sc_s        = (const float*)d_in[14];
    const float* W_sc_v        = (const float*)d_in[15];
    float* out = (float*)d_out;

    cudaFuncSetAttribute(k3_fused, cudaFuncAttributeMaxDynamicSharedMemorySize, K3_SMEM);
    cudaFuncSetAttribute(k4a, cudaFuncAttributeMaxDynamicSharedMemorySize, K4A_SMEM);
    cudaFuncSetAttribute(k4b, cudaFuncAttributeMaxDynamicSharedMemorySize, K4B_SMEM);

    kc_zero<<<40, 512>>>();
    kc_count<<<625, 512>>>(edge_dst);
    k1_lin1<<<148, 256>>>(node_scalars, node_vectors, W_lin1_s, W_lin1_v);
    kc_scan<<<1, 1024>>>();
    kc_scatter<<<625, 512>>>(edge_dst);
    k3_fused<<<1250, 512, K3_SMEM>>>(edge_sh, edge_embedded, edge_src,
                                     W_fc0, W_fc1, W_fc2);
    k4a<<<148, 512, K4A_SMEM>>>(node_scalars, node_attr, W_lin2_s, W_sc_s, out);
    k4b<<<148, 512, K4B_SMEM>>>(node_vectors, node_attr, W_lin2_v, W_sc_v, out);
}

// round 14
// speedup vs baseline: 1.3122x; 1.3122x over previous
#include <cuda_runtime.h>
#include <math.h>

#define N_NODES 20000
#define N_EDGES 320000

// ---------------- scratch (device globals) ----------------
// g_sv per node: s[0:64], v planar: 64 + 64*i + u
__device__ float g_sv[N_NODES * 256];
// g_agg per node, INTERLEAVED: [u][8] with components {A, D, B0, B1, B2, C0, C1, C2}
__device__ float g_agg[N_NODES * 512];
__device__ float g_gate[N_NODES * 64];

__device__ __forceinline__ float silu_n(float x) {
    return 1.679177f * x * (1.0f / (1.0f + __expf(-x)));
}

// ---------------- f32x2 packed-FMA helpers (Blackwell FFMA2) ----------------
typedef unsigned long long u64t;
__device__ __forceinline__ u64t pkdup(float v) {
    u64t r; asm("mov.b64 %0, {%1, %1};" : "=l"(r) : "f"(v)); return r;
}
__device__ __forceinline__ void fma2(u64t& d, u64t a, u64t b) {
    asm("fma.rn.f32x2 %0, %1, %2, %0;" : "+l"(d) : "l"(a), "l"(b));
}
__device__ __forceinline__ float2 up2(u64t v) {
    float2 r; asm("mov.b64 {%0, %1}, %2;" : "=f"(r.x), "=f"(r.y) : "l"(v)); return r;
}
// vectorized global reduction: one RMW op covering 16 B (sm_90+)
__device__ __forceinline__ void red4(float* p, float a, float b, float c, float d) {
    asm volatile("red.global.add.v4.f32 [%0], {%1, %2, %3, %4};"
                 :: "l"(p), "f"(a), "f"(b), "f"(c), "f"(d) : "memory");
}

// ---------------- K1: lin1, persistent blocks, weights staged in smem ----------------
__global__ void __launch_bounds__(256)
k1_lin1(const float* __restrict__ ns, const float* __restrict__ nv,
        const float* __restrict__ W1s, const float* __restrict__ W1v) {
    __shared__ float sWs[4096];
    __shared__ float sWv[4096];
    __shared__ float sIn[4][256];
    int tid = threadIdx.x;
    for (int i = tid; i < 4096; i += 256) {
        sWs[i] = W1s[i] * 0.125f;
        sWv[i] = W1v[i] * 0.125f;
    }
    __syncthreads();
    int w = tid & 63, q = tid >> 6;
    const int ntile = N_NODES / 4;

    for (int tile = blockIdx.x; tile < ntile; tile += gridDim.x) {
        int n0 = tile * 4;
        __syncthreads();
        for (int idx = tid; idx < 1024; idx += 256) {
            int q2 = idx >> 8, r = idx & 255;
            sIn[q2][r] = (r < 64) ? ns[(size_t)(n0 + q2) * 64 + r]
                                  : nv[(size_t)(n0 + q2) * 192 + (r - 64)];
        }
        __syncthreads();
        const float* si = sIn[q];
        float as = 0.f, a0 = 0.f, a1 = 0.f, a2 = 0.f;
#pragma unroll 4
        for (int u = 0; u < 64; u++) {
            float ws = sWs[u * 64 + w];
            float wv = sWv[u * 64 + w];
            as += si[u] * ws;
            a0 += si[64 + 3 * u + 0] * wv;
            a1 += si[64 + 3 * u + 1] * wv;
            a2 += si[64 + 3 * u + 2] * wv;
        }
        float* o = g_sv + (size_t)(n0 + q) * 256;
        o[w] = as;
        o[64 + w] = a0;
        o[128 + w] = a1;
        o[192 + w] = a2;
    }
}

// ---------------- K2: zero the aggregation buffer ----------------
__global__ void k2_zero() {
    int i = blockIdx.x * blockDim.x + threadIdx.x;
    int stride = gridDim.x * blockDim.x;
    float4* p = (float4*)g_agg;
    const int n4 = N_NODES * 512 / 4;
    for (; i < n4; i += stride) p[i] = make_float4(0.f, 0.f, 0.f, 0.f);
}

// ---------------- K3: fused edge MLP + vectorized red.v4 scatter (R9 structure) ----------------
// smem floats: sW0 512 + sW1 4096 + sW2 16384 + 16 warps * 752 = 33024 -> 132096 B
#define K3_SMEM 132096
__global__ void __launch_bounds__(512, 1)
k3_edge(const float* __restrict__ esh, const float* __restrict__ emb,
        const int* __restrict__ esrc, const int* __restrict__ edst,
        const float* __restrict__ W0, const float* __restrict__ W1,
        const float* __restrict__ W2) {
    extern __shared__ float sm[];
    float* sW0 = sm;           // [8][64]   pre-scaled 1/sqrt(8)
    float* sW1 = sm + 512;     // [64][64]  pre-scaled 0.125
    float* sW2 = sm + 4608;    // [64][256] pre-scaled 0.125
    int tid = threadIdx.x;
    for (int i = tid; i < 512; i += 512)   sW0[i] = W0[i] * 0.35355339059327373f;
    for (int i = tid; i < 4096; i += 512)  sW1[i] = W1[i] * 0.125f;
    for (int i = tid; i < 16384; i += 512) sW2[i] = W2[i] * 0.125f;
    __syncthreads();

    int warp = tid >> 5, lane = tid & 31;
    float* pH  = sm + 20992 + warp * 752;  // [row 64][stride 10]
    float* pEB = pH + 640;                 // 64: emb for 8 edges
    float* pSH = pEB + 64;                 // 32: sh for 8 edges
    int*   pIX = (int*)(pSH + 32);         // 16: src[8], dst[8]

    const float inv_sqrt3 = 0.57735026918962576f;
    const int ntile = N_EDGES / 8;  // 40000
    int gw = blockIdx.x * 16 + warp;
    int gstride = gridDim.x * 16;

    for (int tile = gw; tile < ntile; tile += gstride) {
        int e0 = tile * 8;
        // ---- edge meta (coalesced) ----
        if (lane < 16) pIX[lane] = (lane < 8) ? __ldg(esrc + e0 + lane)
                                              : __ldg(edst + e0 + lane - 8);
        pEB[lane]      = __ldg(emb + (size_t)e0 * 8 + lane);
        pEB[lane + 32] = __ldg(emb + (size_t)e0 * 8 + 32 + lane);
        pSH[lane]      = __ldg(esh + (size_t)e0 * 4 + lane);
        __syncwarp();

        // ---- fc0: h0[j][e] (stride 10); lane computes j = lane, lane+32 ----
#pragma unroll
        for (int e = 0; e < 8; e++) {
            float eb[8];
#pragma unroll
            for (int b = 0; b < 8; b++) eb[b] = pEB[e * 8 + b];
#pragma unroll
            for (int jj = 0; jj < 2; jj++) {
                int j = lane + 32 * jj;
                float a = 0.f;
#pragma unroll
                for (int b = 0; b < 8; b++) a += eb[b] * sW0[b * 64 + j];
                pH[j * 10 + e] = silu_n(a);
            }
        }
        __syncwarp();

        // ---- fc1: j = lane, lane+32; edge-paired FFMA2 over all 8 edges ----
        u64t h1[2][4] = {{0ull,0ull,0ull,0ull},{0ull,0ull,0ull,0ull}};
#pragma unroll 4
        for (int k = 0; k < 64; k++) {
            u64t wd0 = pkdup(sW1[k * 64 + lane]);
            u64t wd1 = pkdup(sW1[k * 64 + lane + 32]);
#pragma unroll
            for (int ep = 0; ep < 4; ep++) {
                u64t hp = *(const u64t*)(pH + k * 10 + 2 * ep);
                fma2(h1[0][ep], wd0, hp);
                fma2(h1[1][ep], wd1, hp);
            }
        }
        __syncwarp();
#pragma unroll
        for (int kk = 0; kk < 2; kk++)
#pragma unroll
            for (int ep = 0; ep < 4; ep++) {
                float2 v = up2(h1[kk][ep]);
                pH[(lane + 32 * kk) * 10 + 2 * ep]     = silu_n(v.x);
                pH[(lane + 32 * kk) * 10 + 2 * ep + 1] = silu_n(v.y);
            }
        __syncwarp();

        // ---- fc2: lane owns c = lane + 32j (j=0..7); acc[j][edge-pair] ----
        u64t acc[8][4];
#pragma unroll
        for (int c = 0; c < 8; c++)
#pragma unroll
            for (int ep = 0; ep < 4; ep++) acc[c][ep] = 0ull;
#pragma unroll 2
        for (int k = 0; k < 64; k++) {
            u64t wd[8];
#pragma unroll
            for (int c = 0; c < 8; c++)
                wd[c] = pkdup(sW2[k * 256 + lane + 32 * c]);
#pragma unroll
            for (int ep = 0; ep < 4; ep++) {
                u64t hp = *(const u64t*)(pH + k * 10 + 2 * ep);
#pragma unroll
                for (int c = 0; c < 8; c++) fma2(acc[c][ep], wd[c], hp);
            }
        }
        __syncwarp();

        // ---- epilogue: gather + TWO red.v4 per u (interleaved g_agg [u][8]) ----
#pragma unroll
        for (int e = 0; e < 8; e++) {
            int src = pIX[e], dst = pIX[8 + e];
            src = min(max(src, 0), N_NODES - 1);
            dst = min(max(dst, 0), N_NODES - 1);
            float y0 = pSH[4 * e + 0], Y1 = pSH[4 * e + 1];
            float Y2 = pSH[4 * e + 2], Y3 = pSH[4 * e + 3];
            const float* sv = g_sv + (size_t)src * 256;
            float* ag = g_agg + (size_t)dst * 512;
#pragma unroll
            for (int half = 0; half < 2; half++) {
                int u = lane + 32 * half;
                float2 tA = up2(acc[half][e >> 1]);
                float2 tB = up2(acc[half + 2][e >> 1]);
                float2 tC = up2(acc[half + 4][e >> 1]);
                float2 tD = up2(acc[half + 6][e >> 1]);
                float wA = (e & 1) ? tA.y : tA.x;
                float wB = (e & 1) ? tB.y : tB.x;
                float wC = (e & 1) ? tC.y : tC.x;
                float wD = (e & 1) ? tD.y : tD.x;
                float sA = __ldg(sv + u);
                float v0 = __ldg(sv + 64 + u);
                float v1 = __ldg(sv + 128 + u);
                float v2 = __ldg(sv + 192 + u);
                float vA = wA * sA * y0;
                float vD = wD * (v0 * Y1 + v1 * Y2 + v2 * Y3) * inv_sqrt3;
                float bs = wB * sA;
                float cy = wC * y0;
                float* base = ag + u * 8;
                red4(base,     vA,      vD,      bs * Y1, bs * Y2);
                red4(base + 4, bs * Y3, cy * v0, cy * v1, cy * v2);
            }
        }
        __syncwarp();
    }
}

// ---------------- K4a: s_h = [agg_s | ns(x)attr] @ Wcat, gates + out_s ----------------
#define K4A_SMEM 221184
__global__ void __launch_bounds__(512)
k4a(const float* __restrict__ ns, const float* __restrict__ attr,
    const float* __restrict__ Wl2s, const float* __restrict__ Wscs,
    float* __restrict__ out) {
    extern __shared__ float sm[];
    float* sW = sm;            // [384][128], pre-scaled
    float* sOp = sW + 49152;   // [384][16]
    int tid = threadIdx.x;
    const float lin2n = 0.08838834764831845f;
    const float scn = 0.0625f;
    for (int i = tid; i < 16384; i += 512) sW[i] = Wl2s[i] * lin2n;
    for (int i = tid; i < 32768; i += 512) sW[16384 + i] = Wscs[i] * scn;
    __syncthreads();

    int w = tid & 127, nh = tid >> 7;
    const int ntile = N_NODES / 16;

    for (int tile = blockIdx.x; tile < ntile; tile += gridDim.x) {
        int n0 = tile * 16;
        {
            int k = tid & 127, q = tid >> 7;
            // interleaved layout: A(u) at u*8, D(u) at u*8+1
            int src_idx = (k < 64) ? (k * 8) : ((k - 64) * 8 + 1);
#pragma unroll
            for (int nn = 0; nn < 4; nn++) {
                int node = q * 4 + nn;
                sOp[k * 16 + node] = g_agg[(size_t)(n0 + node) * 512 + src_idx] * 0.0625f;
            }
            for (int idx = tid; idx < 4096; idx += 512) {
                int m = idx >> 4, node = idx & 15;
                sOp[(128 + m) * 16 + node] =
                    ns[(size_t)(n0 + node) * 64 + (m >> 2)] * attr[(size_t)(n0 + node) * 4 + (m & 3)];
            }
        }
        __syncthreads();

        u64t a01 = 0ull, a23 = 0ull;
#pragma unroll 4
        for (int k = 0; k < 384; k++) {
            u64t wd = pkdup(sW[k * 128 + w]);
            ulonglong2 op = *(const ulonglong2*)(sOp + k * 16 + nh * 4);
            fma2(a01, wd, op.x);
            fma2(a23, wd, op.y);
        }
        float2 r01 = up2(a01), r23 = up2(a23);
        float r[4] = {r01.x, r01.y, r23.x, r23.y};
#pragma unroll
        for (int j = 0; j < 4; j++) {
            int n = n0 + nh * 4 + j;
            float val = silu_n(r[j]);
            if (w < 64) out[(size_t)n * 256 + w] = val;
            else        g_gate[(size_t)n * 64 + (w - 64)] = val;
        }
        __syncthreads();
    }
}

// ---------------- K4b: v_h = [agg_v | nv(x)attr] @ Wvcat, gate + out_v ----------------
#define K4B_SMEM 147456
__global__ void __launch_bounds__(512)
k4b(const float* __restrict__ nv, const float* __restrict__ attr,
    const float* __restrict__ Wl2v, const float* __restrict__ Wscv,
    float* __restrict__ out) {
    extern __shared__ float sm[];
    float* sW = sm;            // [384][64], pre-scaled
    float* sOp = sW + 24576;   // [384][8 nodes][4]
    int tid = threadIdx.x;
    const float lin2n = 0.08838834764831845f;
    const float scn = 0.0625f;
    for (int i = tid; i < 8192; i += 512)  sW[i] = Wl2v[i] * lin2n;
    for (int i = tid; i < 16384; i += 512) sW[8192 + i] = Wscv[i] * scn;
    __syncthreads();

    int w = tid & 63, node = tid >> 6;
    const int ntile = N_NODES / 8;

    for (int tile = blockIdx.x; tile < ntile; tile += gridDim.x) {
        int n0 = tile * 8;
        for (int idx = tid; idx < 3072; idx += 512) {
            int k = idx >> 3, nd = idx & 7;
            int n = n0 + nd;
            float o0, o1, o2;
            if (k < 128) {
                // interleaved: B_i(u) at u*8+2+i ; C_i(u) at u*8+5+i
                int u = (k < 64) ? k : (k - 64);
                int base = u * 8 + ((k < 64) ? 2 : 5);
                const float* p = g_agg + (size_t)n * 512 + base;
                o0 = p[0] * 0.0625f; o1 = p[1] * 0.0625f; o2 = p[2] * 0.0625f;
            } else {
                int m = k - 128;
                int u = m >> 2, v = m & 3;
                float av = attr[(size_t)n * 4 + v];
                const float* p = nv + (size_t)n * 192 + u * 3;
                o0 = p[0] * av; o1 = p[1] * av; o2 = p[2] * av;
            }
            *(float4*)(sOp + idx * 4) = make_float4(o0, o1, o2, 0.f);
        }
        __syncthreads();

        u64t a01 = 0ull;
        float a2 = 0.f;
#pragma unroll 4
        for (int k = 0; k < 384; k++) {
            float wk = sW[k * 64 + w];
            u64t wd = pkdup(wk);
            ulonglong2 op = *(const ulonglong2*)(sOp + (k * 8 + node) * 4);
            fma2(a01, wd, op.x);
            float2 t = up2(op.y);
            a2 += wk * t.x;
        }
        int n = n0 + node;
        float gate = g_gate[(size_t)n * 64 + w];
        float2 r = up2(a01);
        float* o = out + (size_t)n * 256 + 64 + 3 * w;
        o[0] = gate * r.x; o[1] = gate * r.y; o[2] = gate * a2;
        __syncthreads();
    }
}

// ---------------- launch ----------------
extern "C" void kernel_launch(void* const* d_in, const int* in_sizes, int n_in,
                              void* d_out, int out_size) {
    const float* node_scalars  = (const float*)d_in[0];
    const float* node_vectors  = (const float*)d_in[1];
    const float* node_attr     = (const float*)d_in[2];
    const float* edge_sh       = (const float*)d_in[3];
    const float* edge_embedded = (const float*)d_in[4];
    const int*   edge_src      = (const int*)d_in[5];
    const int*   edge_dst      = (const int*)d_in[6];
    const float* W_lin1_s      = (const float*)d_in[7];
    const float* W_lin1_v      = (const float*)d_in[8];
    const float* W_fc0         = (const float*)d_in[9];
    const float* W_fc1         = (const float*)d_in[10];
    const float* W_fc2         = (const float*)d_in[11];
    const float* W_lin2_s      = (const float*)d_in[12];
    const float* W_lin2_v      = (const float*)d_in[13];
    const float* W_sc_s        = (const float*)d_in[14];
    const float* W_sc_v        = (const float*)d_in[15];
    float* out = (float*)d_out;

    cudaFuncSetAttribute(k3_edge, cudaFuncAttributeMaxDynamicSharedMemorySize, K3_SMEM);
    cudaFuncSetAttribute(k4a, cudaFuncAttributeMaxDynamicSharedMemorySize, K4A_SMEM);
    cudaFuncSetAttribute(k4b, cudaFuncAttributeMaxDynamicSharedMemorySize, K4B_SMEM);

    k1_lin1<<<148, 256>>>(node_scalars, node_vectors, W_lin1_s, W_lin1_v);
    k2_zero<<<1024, 256>>>();
    k3_edge<<<148, 512, K3_SMEM>>>(edge_sh, edge_embedded, edge_src, edge_dst,
                                   W_fc0, W_fc1, W_fc2);
    k4a<<<148, 512, K4A_SMEM>>>(node_scalars, node_attr, W_lin2_s, W_sc_s, out);
    k4b<<<148, 512, K4B_SMEM>>>(node_vectors, node_attr, W_lin2_v, W_sc_v, out);
}